// round 10
// baseline (speedup 1.0000x reference)
#include <cuda_runtime.h>

#define Hh 51
#define H4 204
#define TT 1024
#define NCTA 128
#define NTHR 640   // warps 0-6: L1 cells (+head in warp 6 hi lanes); warps 7-19: L2 half-cells

// ---- shared memory (float offsets) ----
// sW1 [204][52] W_hh1; sW2i [204][52] W_ih2; sW2h [204][52] W_hh2 (col 51 = 0)
// sWlin[52]; sX [1024][8] t-major
// sH1/sH2: [2 buf][26 kk][4 bp][2 k01][2 b01] = [2][416] floats, k-interleaved:
//   addr(k,b) = (k>>1)*16 + (b>>1)*4 + (k&1)*2 + (b&1)
#define OFF_W1   0
#define OFF_W2I  10608
#define OFF_W2H  21216
#define OFF_WLIN 31824
#define OFF_X    31880
#define OFF_H1   40072   // bytes%128 = 32
#define OFF_H2   40920   // (OFF_H2-OFF_H1)*4 % 128 = 64 -> B's mixed ch0/ch1 loads conflict-free
#define SMEM_FLOATS 41752
#define SMEM_BYTES  (SMEM_FLOATS * 4)

typedef unsigned long long u64;

__device__ __forceinline__ u64 splat2(float w) {
    unsigned int wi = __float_as_uint(w);
    u64 r;
    asm("mov.b64 %0, {%1, %1};" : "=l"(r) : "r"(wi));
    return r;
}
__device__ __forceinline__ void ffma2(u64& d, u64 a, u64 b) {
    asm("fma.rn.f32x2 %0, %1, %2, %0;" : "+l"(d) : "l"(a), "l"(b));
}
__device__ __forceinline__ float2 u2f(u64 v) {
    float2 f;
    asm("mov.b64 {%0, %1}, %2;" : "=f"(f.x), "=f"(f.y) : "l"(v));
    return f;
}
__device__ __forceinline__ u64 f2u(float x, float y) {
    u64 v;
    asm("mov.b64 %0, {%1, %2};" : "=l"(v) : "f"(x), "f"(y));
    return v;
}
__device__ __forceinline__ float sigf(float x) {
    return __fdividef(1.0f, 1.0f + __expf(-x));
}
__device__ __forceinline__ float tanhfast(float x) {
    return 1.0f - __fdividef(2.0f, __expf(2.0f * x) + 1.0f);
}
__device__ __forceinline__ void bar_arrive(int id) {
    asm volatile("bar.arrive %0, %1;" :: "r"(id), "r"(NTHR) : "memory");
}
__device__ __forceinline__ void bar_wait(int id) {
    asm volatile("bar.sync %0, %1;" :: "r"(id), "r"(NTHR) : "memory");
}

// 13 quads (52 k) x 4 gate rows; h in k-interleaved layout (2 LDS.128 per quad)
#define QUADS13(wp0, wp1, wp2, wp3, hb) { \
    _Pragma("unroll") \
    for (int kk = 0; kk < 13; ++kk) { \
        const float4 wi = *(const float4*)((wp0) + kk * 4); \
        const float4 wf = *(const float4*)((wp1) + kk * 4); \
        const float4 wg = *(const float4*)((wp2) + kk * 4); \
        const float4 wo = *(const float4*)((wp3) + kk * 4); \
        const ulonglong2 v0 = *(const ulonglong2*)((hb) + kk * 32); \
        const ulonglong2 v1 = *(const ulonglong2*)((hb) + kk * 32 + 16); \
        ffma2(ai, splat2(wi.x), v0.x); ffma2(ai, splat2(wi.y), v0.y); \
        ffma2(ai, splat2(wi.z), v1.x); ffma2(ai, splat2(wi.w), v1.y); \
        ffma2(af, splat2(wf.x), v0.x); ffma2(af, splat2(wf.y), v0.y); \
        ffma2(af, splat2(wf.z), v1.x); ffma2(af, splat2(wf.w), v1.y); \
        ffma2(ag, splat2(wg.x), v0.x); ffma2(ag, splat2(wg.y), v0.y); \
        ffma2(ag, splat2(wg.z), v1.x); ffma2(ag, splat2(wg.w), v1.y); \
        ffma2(ao, splat2(wo.x), v0.x); ffma2(ao, splat2(wo.y), v0.y); \
        ffma2(ao, splat2(wo.z), v1.x); ffma2(ao, splat2(wo.w), v1.y); \
    } }

#define UPDATE(cvar, hout) { \
    const float2 gi = u2f(ai), gf = u2f(af), gg = u2f(ag), go = u2f(ao); \
    const float i0 = sigf(gi.x), f0 = sigf(gf.x), g0 = tanhfast(gg.x), o0 = sigf(go.x); \
    const float i1 = sigf(gi.y), f1 = sigf(gf.y), g1 = tanhfast(gg.y), o1 = sigf(go.y); \
    cvar.x = f0 * cvar.x + i0 * g0; \
    cvar.y = f1 * cvar.y + i1 * g1; \
    hout = f2u(o0 * tanhfast(cvar.x), o1 * tanhfast(cvar.y)); }

__global__ __launch_bounds__(NTHR, 1)
void lstm_seq_kernel(const float* __restrict__ input,
                     const float* __restrict__ W_ih1, const float* __restrict__ W_hh1,
                     const float* __restrict__ b_ih1, const float* __restrict__ b_hh1,
                     const float* __restrict__ W_ih2, const float* __restrict__ W_hh2,
                     const float* __restrict__ b_ih2, const float* __restrict__ b_hh2,
                     const float* __restrict__ W_lin, const float* __restrict__ b_lin,
                     float* __restrict__ out)
{
    extern __shared__ float sm[];
    float* sW1   = sm + OFF_W1;
    float* sW2i  = sm + OFF_W2I;
    float* sW2h  = sm + OFF_W2H;
    float* sWlin = sm + OFF_WLIN;
    float* sX    = sm + OFF_X;
    float* sH1   = sm + OFF_H1;   // [2][416]
    float* sH2   = sm + OFF_H2;   // [2][416]

    const int tid = threadIdx.x;
    const int b0  = blockIdx.x * 8;

    // ---------------- staging ----------------
    for (int i = tid; i < H4 * Hh; i += NTHR) {
        const int r = i / Hh, k = i % Hh;
        sW1[r * 52 + k]  = W_hh1[i];
        sW2i[r * 52 + k] = W_ih2[i];
        sW2h[r * 52 + k] = W_hh2[i];
    }
    for (int r = tid; r < H4; r += NTHR) {
        sW1[r * 52 + 51]  = 0.0f;
        sW2i[r * 52 + 51] = 0.0f;
        sW2h[r * 52 + 51] = 0.0f;
    }
    if (tid < 52) sWlin[tid] = (tid < Hh) ? W_lin[tid] : 0.0f;
    for (int i = tid; i < 8 * TT; i += NTHR) {
        const int b = i >> 10, t = i & 1023;
        sX[t * 8 + b] = input[b0 * TT + i];
    }
    for (int i = tid; i < (OFF_H2 - OFF_H1) + 832; i += NTHR) sH1[i] = 0.0f;

    // ---------------- roles ----------------
    const bool isA = (tid < 224);
    const float blin = b_lin[0];

    // ----- A: jA = tid>>2 (0..55), bp = tid&3 -----
    const int jA  = tid >> 2;
    const int boA = (tid & 3) * 2;
    const bool actA = isA && (jA < Hh);
    u64 bA_i = 0, bA_f = 0, bA_g = 0, bA_o = 0;
    u64 wxi = 0, wxf = 0, wxg = 0, wxo = 0;
    const float* wA0 = sW1; const float* wA1 = sW1;
    const float* wA2 = sW1; const float* wA3 = sW1;
    if (actA) {
        const int ri = jA, rf = Hh + jA, rg = 2 * Hh + jA, ro = 3 * Hh + jA;
        bA_i = splat2(b_ih1[ri] + b_hh1[ri]);
        bA_f = splat2(b_ih1[rf] + b_hh1[rf]);
        bA_g = splat2(b_ih1[rg] + b_hh1[rg]);
        bA_o = splat2(b_ih1[ro] + b_hh1[ro]);
        wxi = splat2(W_ih1[ri]); wxf = splat2(W_ih1[rf]);
        wxg = splat2(W_ih1[rg]); wxo = splat2(W_ih1[ro]);
        wA0 = sW1 + ri * 52; wA1 = sW1 + rf * 52;
        wA2 = sW1 + rg * 52; wA3 = sW1 + ro * 52;
    }
    // A store offset: h1[jA][2bp..2bp+1]
    const int stoA = (jA >> 1) * 16 + (tid & 3) * 4 + (jA & 1) * 2;

    // ----- B: bt = tid-224: bp = bt&3, ch = bit2, j = bt>>3 -----
    const int bt  = tid - 224;                 // 0..415
    const int bpB = bt & 3;
    const int chB = (bt >> 2) & 1;
    const int jBr = bt >> 3;                   // 0..51
    const bool actB = !isA && (jBr < Hh);
    const int jB = (jBr < Hh) ? jBr : (Hh - 1);
    u64 sB_i = 0, sB_f = 0, sB_g = 0, sB_o = 0;
    const float* wB0 = sW2i; const float* wB1 = sW2i;
    const float* wB2 = sW2i; const float* wB3 = sW2i;
    if (!isA) {
        const int ri = jB, rf = Hh + jB, rg = 2 * Hh + jB, ro = 3 * Hh + jB;
        if (chB == 0) {
            sB_i = splat2(b_ih2[ri] + b_hh2[ri]);
            sB_f = splat2(b_ih2[rf] + b_hh2[rf]);
            sB_g = splat2(b_ih2[rg] + b_hh2[rg]);
            sB_o = splat2(b_ih2[ro] + b_hh2[ro]);
            wB0 = sW2i + ri * 52; wB1 = sW2i + rf * 52;
            wB2 = sW2i + rg * 52; wB3 = sW2i + ro * 52;
        } else {
            wB0 = sW2h + ri * 52; wB1 = sW2h + rf * 52;
            wB2 = sW2h + rg * 52; wB3 = sW2h + ro * 52;
        }
    }
    const int stoB = (jB >> 1) * 16 + bpB * 4 + (jB & 1) * 2;

    // ----- head: tids 208..223 (warp 6 lanes 16..31; jA>=52 there) -----
    const int hl  = tid - 208;        // 0..15 valid
    const int hbb = hl & 7;           // batch
    const int hkq = (hl >> 3) & 1;    // k half

    float2 c1 = make_float2(0.0f, 0.0f);
    float2 c2 = make_float2(0.0f, 0.0f);

    __syncthreads();

    // ---------------- prologue ----------------
    if (isA) {
        if (actA) {
            // h1(0): x(0), h1(-1)=0 (buf 1 zeros)
            u64 ai = bA_i, af = bA_f, ag = bA_g, ao = bA_o;
            const u64 xv = *(const u64*)(sX + boA);
            ffma2(ai, wxi, xv); ffma2(af, wxf, xv);
            ffma2(ag, wxg, xv); ffma2(ao, wxo, xv);
            const float* hb = sH1 + 416 + (tid & 3) * 4;
            QUADS13(wA0, wA1, wA2, wA3, hb);
            u64 hnew;
            UPDATE(c1, hnew);
            *(u64*)(sH1 + stoA) = hnew;        // buf 0
        }
        bar_arrive(1);                          // gen 0: h1(0) ready
    } else {
        bar_arrive(2);                          // gen 0: buffers free
    }

    // ---------------- time loop ----------------
    for (int t = 0; t < TT; ++t) {
        const int pt = t & 1, pn = pt ^ 1;

        if (isA) {
            bar_wait(2);                        // gen t: B(t-1) done
            if (actA) {
                if (t < TT - 1) {
                    // h1(t+1): x(t+1), h1(t)[pt] -> buf pn
                    u64 ai = bA_i, af = bA_f, ag = bA_g, ao = bA_o;
                    const u64 xv = *(const u64*)(sX + (t + 1) * 8 + boA);
                    ffma2(ai, wxi, xv); ffma2(af, wxf, xv);
                    ffma2(ag, wxg, xv); ffma2(ao, wxo, xv);
                    const float* hb = sH1 + pt * 416 + (tid & 3) * 4;
                    QUADS13(wA0, wA1, wA2, wA3, hb);
                    u64 hnew;
                    UPDATE(c1, hnew);
                    *(u64*)(sH1 + pn * 416 + stoA) = hnew;
                }
            } else if (hl >= 0 && hl < 16 && t >= 1) {
                // head(t-1): reads h2(t-1)[buf pn]
                const float* h2r = sH2 + pn * 416;
                float p = 0.0f;
                #pragma unroll
                for (int s = 0; s < 26; ++s) {
                    const int k = hkq * 26 + s;
                    if (k < Hh)
                        p = fmaf(sWlin[k],
                                 h2r[(k >> 1) * 16 + (hbb >> 1) * 4 + (k & 1) * 2 + (hbb & 1)],
                                 p);
                }
                p += __shfl_xor_sync(0xFFFF0000u, p, 8);
                if (hkq == 0)
                    out[(b0 + hbb) * TT + (t - 1)] = p + blin;
            }
            if (t < TT - 1) bar_arrive(1);      // gen t+1: h1(t+1) ready
        } else {
            bar_wait(1);                        // gen t: h1(t) ready
            // L2 cell(t): ch0 = ih2 half (h1(t)[pt]), ch1 = hh2 half (h2(t-1)[pn])
            u64 ai = sB_i, af = sB_f, ag = sB_g, ao = sB_o;
            const float* hb = (chB ? (sH2 + pn * 416) : (sH1 + pt * 416)) + bpB * 4;
            QUADS13(wB0, wB1, wB2, wB3, hb);
            {
                u64 x;
                x = __shfl_xor_sync(0xffffffffu, ai, 4);
                asm("add.rn.f32x2 %0, %0, %1;" : "+l"(ai) : "l"(x));
                x = __shfl_xor_sync(0xffffffffu, af, 4);
                asm("add.rn.f32x2 %0, %0, %1;" : "+l"(af) : "l"(x));
                x = __shfl_xor_sync(0xffffffffu, ag, 4);
                asm("add.rn.f32x2 %0, %0, %1;" : "+l"(ag) : "l"(x));
                x = __shfl_xor_sync(0xffffffffu, ao, 4);
                asm("add.rn.f32x2 %0, %0, %1;" : "+l"(ao) : "l"(x));
            }
            u64 hnew;
            UPDATE(c2, hnew);
            if (actB && chB == 0)
                *(u64*)(sH2 + pt * 416 + stoB) = hnew;   // h2(t)
            bar_arrive(2);                      // gen t+1
        }
    }

    // ---------------- epilogue: head(TT-1) ----------------
    if (isA) {
        bar_wait(2);                            // gen TT: B(TT-1) done
        if (hl >= 0 && hl < 16) {
            const float* h2r = sH2 + ((TT - 1) & 1) * 416;
            float p = 0.0f;
            #pragma unroll
            for (int s = 0; s < 26; ++s) {
                const int k = hkq * 26 + s;
                if (k < Hh)
                    p = fmaf(sWlin[k],
                             h2r[(k >> 1) * 16 + (hbb >> 1) * 4 + (k & 1) * 2 + (hbb & 1)],
                             p);
            }
            p += __shfl_xor_sync(0xFFFF0000u, p, 8);
            if (hkq == 0)
                out[(b0 + hbb) * TT + (TT - 1)] = p + blin;
        }
    }
}

extern "C" void kernel_launch(void* const* d_in, const int* in_sizes, int n_in,
                              void* d_out, int out_size) {
    const float* input = (const float*)d_in[0];
    const float* W_ih1 = (const float*)d_in[1];
    const float* W_hh1 = (const float*)d_in[2];
    const float* b_ih1 = (const float*)d_in[3];
    const float* b_hh1 = (const float*)d_in[4];
    const float* W_ih2 = (const float*)d_in[5];
    const float* W_hh2 = (const float*)d_in[6];
    const float* b_ih2 = (const float*)d_in[7];
    const float* b_hh2 = (const float*)d_in[8];
    const float* W_lin = (const float*)d_in[9];
    const float* b_lin = (const float*)d_in[10];
    float* out = (float*)d_out;

    cudaFuncSetAttribute(lstm_seq_kernel,
                         cudaFuncAttributeMaxDynamicSharedMemorySize, SMEM_BYTES);
    lstm_seq_kernel<<<NCTA, NTHR, SMEM_BYTES>>>(
        input, W_ih1, W_hh1, b_ih1, b_hh1,
        W_ih2, W_hh2, b_ih2, b_hh2, W_lin, b_lin, out);
}